// round 11
// baseline (speedup 1.0000x reference)
#include <cuda_runtime.h>
#include <cuda_fp16.h>
#include <cstdint>

// ArcFace loss, fused, single-pass W. FP16 HMMA (m16n8k16.f16), warp 64x64,
// fp16 accumulate. k2 reads raw fp32 W once: cp.async -> smem fp32 staging ->
// cooperative cvt to fp16 smem + |W_row|^2 accumulation -> mma. No k1b pass.
// B=512, D=512, C=64000.
constexpr int BB = 512;
constexpr int DD = 512;
constexpr int CC = 64000;

constexpr int BM = 256, BN = 128, BK = 32;
constexpr int MT = BB / BM;    // 2
constexpr int NT = CC / BN;    // 500
constexpr int NSTG = DD / BK;  // 16
constexpr int AROW = 40;       // fp16 smem row stride (halfs); ldsm conflict-free
constexpr int A_STG = BM * AROW * 2;    // 20480 B
constexpr int B16_STG = BN * AROW * 2;  // 10240 B
constexpr int B32_ROW = 144;            // fp32 staging row stride bytes (128+16 pad)
constexpr int B32_STG = BN * B32_ROW;   // 18432 B

// dynamic smem layout
constexpr int A_OFF   = 0;                    // 3 stages
constexpr int B32_OFF = 3 * A_STG;            // 61440, 2 buffers
constexpr int B16_OFF = B32_OFF + 2 * B32_STG;// 98304, 1 buffer
constexpr int SY_OFF  = B16_OFF + B16_STG;    // 108544: 256 ints
constexpr int NP_OFF  = SY_OFF + 1024;        // 109568: 256 floats
constexpr int RN_OFF  = NP_OFF + 1024;        // 110592: 128 floats
constexpr int RA_OFF  = RN_OFF + 512;         // 111104: 256x2 floats
constexpr int SMEM_TOTAL = RA_OFF + 2048;     // 113152 (x2 CTA = 226KB <= 228KB)

__device__ float  g_xn[BB * DD];    // normalized x fp32 (k3 exact dot)
__device__ __half g_xnh[BB * DD];   // normalized x fp16 (GEMM A)
__device__ int    g_y[BB];
__device__ float  g_partial[MT * NT * BM];
__device__ double g_term[BB];

// ---------------- PTX helpers ----------------
__device__ __forceinline__ void ldsm4(uint32_t* r, uint32_t a) {
    asm volatile("ldmatrix.sync.aligned.m8n8.x4.shared.b16 {%0,%1,%2,%3}, [%4];"
        : "=r"(r[0]), "=r"(r[1]), "=r"(r[2]), "=r"(r[3]) : "r"(a));
}
__device__ __forceinline__ void mma16816h(uint32_t* c, const uint32_t* a, uint32_t b0, uint32_t b1) {
    asm volatile("mma.sync.aligned.m16n8k16.row.col.f16.f16.f16.f16 "
        "{%0,%1}, {%2,%3,%4,%5}, {%6,%7}, {%0,%1};"
        : "+r"(c[0]), "+r"(c[1])
        : "r"(a[0]), "r"(a[1]), "r"(a[2]), "r"(a[3]), "r"(b0), "r"(b1));
}
__device__ __forceinline__ void cpasync16(uint32_t smem, const void* gptr) {
    asm volatile("cp.async.cg.shared.global [%0], [%1], 16;"
        :: "r"(smem), "l"(gptr) : "memory");
}
__device__ __forceinline__ void cpcommit() { asm volatile("cp.async.commit_group;" ::: "memory"); }
__device__ __forceinline__ void cpwait1() { asm volatile("cp.async.wait_group 1;" ::: "memory"); }

// ---------------------------------------------------------------------------
// k1: L2-normalize rows of x -> fp32 + fp16; block 0 also decodes labels
// (int64 vs int32 layout sniff: labels < 64000 -> int64 high words all zero).
// ---------------------------------------------------------------------------
__global__ void k1_norm_x(const float* __restrict__ x, const int* __restrict__ yw) {
    int row = blockIdx.x;
    int t = threadIdx.x; // 128
    float4 v = ((const float4*)(x + row * DD))[t];
    float ss = v.x * v.x + v.y * v.y + v.z * v.z + v.w * v.w;
    #pragma unroll
    for (int o = 16; o; o >>= 1) ss += __shfl_xor_sync(0xffffffffu, ss, o);
    __shared__ float ws[4];
    if ((t & 31) == 0) ws[t >> 5] = ss;
    __syncthreads();
    float tot = ws[0] + ws[1] + ws[2] + ws[3];
    float sc = 1.0f / fmaxf(sqrtf(tot), 1e-12f);
    float4 o4 = make_float4(v.x * sc, v.y * sc, v.z * sc, v.w * sc);
    ((float4*)(g_xn + row * DD))[t] = o4;
    __half2 p0 = __floats2half2_rn(o4.x, o4.y);
    __half2 p1 = __floats2half2_rn(o4.z, o4.w);
    ((__half2*)(g_xnh + row * DD))[2 * t]     = p0;
    ((__half2*)(g_xnh + row * DD))[2 * t + 1] = p1;

    if (row == 0) {
        __shared__ int oddnz;
        if (t == 0) oddnz = 0;
        __syncthreads();
        int nz = 0;
        for (int i = t; i < 256; i += 128)
            if (yw[2 * i + 1] != 0) nz = 1;
        if (nz) atomicOr(&oddnz, 1);
        __syncthreads();
        for (int i = t; i < BB; i += 128)
            g_y[i] = oddnz ? yw[i] : (int)((const long long*)yw)[i];
    }
}

// ---------------------------------------------------------------------------
// k2: fused GEMM. 256 threads / 8 warps (4x2, warp tile 64x64), 256Mx128N,
// BK=32. A: fp16 cp.async 3-stage. B: fp32 W cp.async -> staging (2 bufs) ->
// cooperative cvt to single fp16 buffer + |W_row|^2 accumulation. fp16 acc.
// Epilogue: theta = acc / |W_row|; exp + target mask + row-sum -> g_partial.
// ---------------------------------------------------------------------------
__global__ __launch_bounds__(256, 2) void k2_gemm(const float* __restrict__ Wm) {
    extern __shared__ char smem[];
    const uint32_t sb = (uint32_t)__cvta_generic_to_shared(smem);
    const int t = threadIdx.x, lane = t & 31, wp = t >> 5;
    const int wm = wp >> 1, wn = wp & 1;       // 4x2 warps, warp tile 64x64
    const int mt = blockIdx.x, nt = blockIdx.y;
    const int m0 = mt * BM, n0 = nt * BN;

    if (t < BM) ((int*)(smem + SY_OFF))[t] = g_y[m0 + t];

    // A producer: rows t>>2 (+0/64/128/192), col chunk (t&3)*8 halfs
    const int apr = t >> 2, apc = (t & 3) * 8;
    const __half* gA = g_xnh + (m0 + apr) * DD + apc;
    const uint32_t sA = sb + A_OFF + (apr * AROW + apc) * 2;
    constexpr uint32_t ARS = 64 * AROW * 2;
    // B fp32 producer: row t>>1, float chunk (t&1)*16, 4x16B
    const int bpr = t >> 1, bpc = (t & 1) * 16;
    const float* gB = Wm + (size_t)(n0 + bpr) * DD + bpc;
    const uint32_t sB32 = sb + B32_OFF + bpr * B32_ROW + bpc * 4;
    uint32_t woA = 0;
    uint32_t wb32 = 0;

    auto fill = [&]() {
        cpasync16(sA + woA,           gA);
        cpasync16(sA + woA + ARS,     gA + 64 * DD);
        cpasync16(sA + woA + 2 * ARS, gA + 128 * DD);
        cpasync16(sA + woA + 3 * ARS, gA + 192 * DD);
        uint32_t b = sB32 + wb32;
        cpasync16(b,      gB);
        cpasync16(b + 16, gB + 4);
        cpasync16(b + 32, gB + 8);
        cpasync16(b + 48, gB + 12);
        gA += BK; gB += BK;
        woA += A_STG; if (woA == 3 * A_STG) woA = 0;
        wb32 ^= B32_STG;
    };

    uint32_t acc[4][8][2];   // fp16x2 accumulators
    #pragma unroll
    for (int i = 0; i < 4; i++)
        #pragma unroll
        for (int j = 0; j < 8; j++) { acc[i][j][0] = 0u; acc[i][j][1] = 0u; }

    uint32_t aoff[4], boff[4];
    #pragma unroll
    for (int mf = 0; mf < 4; mf++)
        aoff[mf] = sb + A_OFF + ((wm * 64 + mf * 16 + (lane & 15)) * AROW + (lane >> 4) * 8) * 2;
    #pragma unroll
    for (int g = 0; g < 4; g++)
        boff[g] = sb + B16_OFF + ((wn * 64 + g * 16 + (lane & 15)) * AROW + (lane >> 4) * 8) * 2;

    // convert-side addresses (this thread converts row bpr, 16 floats at bpc)
    const char* cvsrc_base = smem + B32_OFF + bpr * B32_ROW + bpc * 4;
    char* cvdst = smem + B16_OFF + (bpr * AROW + bpc) * 2;
    float nacc = 0.f;

    fill(); cpcommit();
    fill(); cpcommit();

    uint32_t roA = 0;
    uint32_t rb32 = 0;
    for (int ks = 0; ks < NSTG; ks++) {
        cpwait1();
        __syncthreads();   // A(ks), Bf32(ks) visible; Bf16 free (mma ks-1 done)

        // ---- convert Bf32(ks) -> Bf16, accumulate |W_row|^2
        {
            const char* src = cvsrc_base + rb32;
            float4 f0 = *(const float4*)(src);
            float4 f1 = *(const float4*)(src + 16);
            float4 f2 = *(const float4*)(src + 32);
            float4 f3 = *(const float4*)(src + 48);
            nacc += f0.x * f0.x + f0.y * f0.y + f0.z * f0.z + f0.w * f0.w
                  + f1.x * f1.x + f1.y * f1.y + f1.z * f1.z + f1.w * f1.w
                  + f2.x * f2.x + f2.y * f2.y + f2.z * f2.z + f2.w * f2.w
                  + f3.x * f3.x + f3.y * f3.y + f3.z * f3.z + f3.w * f3.w;
            __half2 h0 = __floats2half2_rn(f0.x, f0.y);
            __half2 h1 = __floats2half2_rn(f0.z, f0.w);
            __half2 h2 = __floats2half2_rn(f1.x, f1.y);
            __half2 h3 = __floats2half2_rn(f1.z, f1.w);
            __half2 h4 = __floats2half2_rn(f2.x, f2.y);
            __half2 h5 = __floats2half2_rn(f2.z, f2.w);
            __half2 h6 = __floats2half2_rn(f3.x, f3.y);
            __half2 h7 = __floats2half2_rn(f3.z, f3.w);
            uint4 u0, u1;
            u0.x = *(uint32_t*)&h0; u0.y = *(uint32_t*)&h1;
            u0.z = *(uint32_t*)&h2; u0.w = *(uint32_t*)&h3;
            u1.x = *(uint32_t*)&h4; u1.y = *(uint32_t*)&h5;
            u1.z = *(uint32_t*)&h6; u1.w = *(uint32_t*)&h7;
            *(uint4*)(cvdst)      = u0;
            *(uint4*)(cvdst + 16) = u1;
            rb32 ^= B32_STG;
        }
        __syncthreads();   // Bf16 ready; Bf32 buf (ks&1) free

        if (ks + 2 < NSTG) fill();
        cpcommit();

        #pragma unroll
        for (int kc = 0; kc < 2; kc++) {
            uint32_t bfrag[4][4];
            #pragma unroll
            for (int g = 0; g < 4; g++)
                ldsm4(bfrag[g], boff[g] + kc * 32);
            #pragma unroll
            for (int mf = 0; mf < 4; mf++) {
                uint32_t afrag[4];
                ldsm4(afrag, aoff[mf] + roA + kc * 32);
                #pragma unroll
                for (int nf = 0; nf < 8; nf++) {
                    int g = nf >> 1, h = nf & 1;
                    mma16816h(acc[mf][nf], afrag, bfrag[g][h], bfrag[g][2 + h]);
                }
            }
        }
        roA += A_STG; if (roA == 3 * A_STG) roA = 0;
    }

    // ---- column norms (deterministic order: 2 partials per row)
    ((float*)(smem + NP_OFF))[bpr * 2 + (t & 1)] = nacc;
    __syncthreads();
    if (t < BN) {
        const float* np = (const float*)(smem + NP_OFF);
        float s = np[t * 2] + np[t * 2 + 1];
        ((float*)(smem + RN_OFF))[t] = 1.0f / fmaxf(sqrtf(s), 1e-12f);
    }
    __syncthreads();

    // ---- epilogue: theta = acc * rn[col]; exp + mask + row-sum
    const int*   sy = (const int*)(smem + SY_OFF);
    const float* rn = (const float*)(smem + RN_OFF);
    float* rowacc = (float*)(smem + RA_OFF);
    float2 rn2[8];
    #pragma unroll
    for (int nf = 0; nf < 8; nf++)
        rn2[nf] = *(const float2*)&rn[wn * 64 + nf * 8 + (lane & 3) * 2];

    #pragma unroll
    for (int mf = 0; mf < 4; mf++) {
        #pragma unroll
        for (int h = 0; h < 2; h++) {
            int row = wm * 64 + mf * 16 + h * 8 + (lane >> 2);
            int yrel = sy[row] - n0;
            float rsum = 0.f;
            #pragma unroll
            for (int nf = 0; nf < 8; nf++) {
                int nl = wn * 64 + nf * 8 + (lane & 3) * 2;
                float2 th = __half22float2(*(const __half2*)&acc[mf][nf][h]);
                float e0 = __expf(64.0f * th.x * rn2[nf].x);
                float e1 = __expf(64.0f * th.y * rn2[nf].y);
                rsum += (nl     == yrel) ? 0.f : e0;
                rsum += (nl + 1 == yrel) ? 0.f : e1;
            }
            rsum += __shfl_xor_sync(0xffffffffu, rsum, 1);
            rsum += __shfl_xor_sync(0xffffffffu, rsum, 2);
            if ((lane & 3) == 0) rowacc[row * 2 + wn] = rsum;
        }
    }
    __syncthreads();
    if (t < BM)
        g_partial[(mt * NT + nt) * BM + t] = rowacc[t * 2] + rowacc[t * 2 + 1];
}

// ---------------------------------------------------------------------------
// k3: per-row finalize; exact fp32 target logit. One block per row, 512 thr.
// ---------------------------------------------------------------------------
__global__ __launch_bounds__(512) void k3_final(const float* __restrict__ Wm) {
    __shared__ double sd[512];
    __shared__ float  sf[128], sg[128];
    int b = blockIdx.x, t = threadIdx.x;
    int yb = g_y[b];
    int mt = b >> 8, ml = b & 255;

    double ex = (t < NT) ? (double)g_partial[(mt * NT + t) * BM + ml] : 0.0;

    if (t < 128) {
        float4 wv = ((const float4*)(Wm + (size_t)yb * DD))[t];
        float4 xv = ((const float4*)(g_xn + b * DD))[t];
        sf[t] = wv.x * xv.x + wv.y * xv.y + wv.z * xv.z + wv.w * xv.w;
        sg[t] = wv.x * wv.x + wv.y * wv.y + wv.z * wv.z + wv.w * wv.w;
    }
    sd[t] = ex;
    __syncthreads();
    for (int s = 256; s >= 128; s >>= 1) {
        if (t < s) sd[t] += sd[t + s];
        __syncthreads();
    }
    for (int s = 64; s; s >>= 1) {
        if (t < s) { sd[t] += sd[t + s]; sf[t] += sf[t + s]; sg[t] += sg[t + s]; }
        __syncthreads();
    }
    if (t == 0) {
        double tgt = (double)sf[0] / fmax(sqrt((double)sg[0]), 1e-12);
        double tc = fmin(fmax(tgt, -1.0 + 1e-7), 1.0 - 1e-7);
        double num = 64.0 * cos(acos(tc) + 0.5);
        double den = exp(num) + sd[0];
        g_term[b] = num - log(den);
    }
}

__global__ void k4_reduce(float* __restrict__ out) {
    __shared__ double sm[BB];
    int t = threadIdx.x;
    sm[t] = g_term[t];
    __syncthreads();
    for (int s = BB / 2; s; s >>= 1) {
        if (t < s) sm[t] += sm[t + s];
        __syncthreads();
    }
    if (t == 0) out[0] = (float)(-sm[0] / (double)BB);
}

extern "C" void kernel_launch(void* const* d_in, const int* in_sizes, int n_in,
                              void* d_out, int out_size) {
    const float* x = (const float*)d_in[0];
    const int*   y = (const int*)d_in[1];
    const float* W = (const float*)d_in[2];

    cudaFuncSetAttribute(k2_gemm, cudaFuncAttributeMaxDynamicSharedMemorySize, SMEM_TOTAL);

    k1_norm_x<<<BB, 128>>>(x, y);
    k2_gemm<<<dim3(MT, NT), 256, SMEM_TOTAL>>>(W);
    k3_final<<<BB, 512>>>(W);
    k4_reduce<<<1, BB>>>((float*)d_out);
}

// round 12
// speedup vs baseline: 1.0943x; 1.0943x over previous
#include <cuda_runtime.h>
#include <cuda_fp16.h>
#include <cstdint>

// ArcFace loss, fused. FP16 HMMA (m16n8k16.f16), warp tile 64x64, fp16 acc.
// k2 = round-10 best (109.4us). This round: k0 fused into k1, k4 fused into
// k3 (last-block-done deterministic reduction).
// B=512, D=512, C=64000.
constexpr int BB = 512;
constexpr int DD = 512;
constexpr int CC = 64000;

constexpr int BM = 256, BN = 128, BK = 32;
constexpr int MT = BB / BM;    // 2
constexpr int NT = CC / BN;    // 500
constexpr int NSTG = DD / BK;  // 16
constexpr int AROW = 40;       // smem row stride (halfs); ldsm conflict-free
constexpr int A_STG = BM * AROW * 2;   // 20480 B
constexpr int B_STG = BN * AROW * 2;   // 10240 B
constexpr int NPIPE = 3;

// dynamic smem layout
constexpr int A_OFF  = 0;                       // 3 stages
constexpr int B_OFF  = NPIPE * A_STG;           // 61440, 3 stages
constexpr int SY_OFF = B_OFF + NPIPE * B_STG;   // 92160: 256 ints
constexpr int RA_OFF = SY_OFF + 1024;           // 93184: 256x2 floats
constexpr int SMEM_TOTAL = RA_OFF + 2048;       // 95232 (x2 CTA = 190KB <= 228KB)

__device__ float  g_xn[BB * DD];    // normalized x fp32 (k3 exact dot)
__device__ __half g_xnh[BB * DD];   // normalized x fp16 (GEMM A)
__device__ __half g_wnh[CC * DD];   // normalized W fp16 (GEMM B)
__device__ int    g_y[BB];
__device__ float  g_partial[MT * NT * BM];
__device__ double g_term[BB];
__device__ unsigned int g_k3done;   // zero-initialized; reset by finisher

// ---------------- PTX helpers ----------------
__device__ __forceinline__ void ldsm4(uint32_t* r, uint32_t a) {
    asm volatile("ldmatrix.sync.aligned.m8n8.x4.shared.b16 {%0,%1,%2,%3}, [%4];"
        : "=r"(r[0]), "=r"(r[1]), "=r"(r[2]), "=r"(r[3]) : "r"(a));
}
__device__ __forceinline__ void mma16816h(uint32_t* c, const uint32_t* a, uint32_t b0, uint32_t b1) {
    asm volatile("mma.sync.aligned.m16n8k16.row.col.f16.f16.f16.f16 "
        "{%0,%1}, {%2,%3,%4,%5}, {%6,%7}, {%0,%1};"
        : "+r"(c[0]), "+r"(c[1])
        : "r"(a[0]), "r"(a[1]), "r"(a[2]), "r"(a[3]), "r"(b0), "r"(b1));
}
__device__ __forceinline__ void cpasync16(uint32_t smem, const void* gptr) {
    asm volatile("cp.async.cg.shared.global [%0], [%1], 16;"
        :: "r"(smem), "l"(gptr) : "memory");
}
__device__ __forceinline__ void cpcommit() { asm volatile("cp.async.commit_group;" ::: "memory"); }
__device__ __forceinline__ void cpwait1() { asm volatile("cp.async.wait_group 1;" ::: "memory"); }

// ---------------------------------------------------------------------------
// k1: L2-normalize rows of x -> fp32 + fp16; block 0 also decodes labels
// (int64 vs int32 layout sniff: labels < 64000 -> int64 high words all zero).
// ---------------------------------------------------------------------------
__global__ void k1_norm_x(const float* __restrict__ x, const int* __restrict__ yw) {
    int row = blockIdx.x;
    int t = threadIdx.x; // 128
    float4 v = ((const float4*)(x + row * DD))[t];
    float ss = v.x * v.x + v.y * v.y + v.z * v.z + v.w * v.w;
    #pragma unroll
    for (int o = 16; o; o >>= 1) ss += __shfl_xor_sync(0xffffffffu, ss, o);
    __shared__ float ws[4];
    if ((t & 31) == 0) ws[t >> 5] = ss;
    __syncthreads();
    float tot = ws[0] + ws[1] + ws[2] + ws[3];
    float sc = 1.0f / fmaxf(sqrtf(tot), 1e-12f);
    float4 o4 = make_float4(v.x * sc, v.y * sc, v.z * sc, v.w * sc);
    ((float4*)(g_xn + row * DD))[t] = o4;
    __half2 p0 = __floats2half2_rn(o4.x, o4.y);
    __half2 p1 = __floats2half2_rn(o4.z, o4.w);
    ((__half2*)(g_xnh + row * DD))[2 * t]     = p0;
    ((__half2*)(g_xnh + row * DD))[2 * t + 1] = p1;

    if (row == 0) {
        __shared__ int oddnz;
        if (t == 0) oddnz = 0;
        __syncthreads();
        int nz = 0;
        for (int i = t; i < 256; i += 128)
            if (yw[2 * i + 1] != 0) nz = 1;
        if (nz) atomicOr(&oddnz, 1);
        __syncthreads();
        for (int i = t; i < BB; i += 128)
            g_y[i] = oddnz ? yw[i] : (int)((const long long*)yw)[i];
    }
}

// k1b: L2-normalize rows of W -> fp16. One warp per row, 8 rows per block.
__global__ __launch_bounds__(256) void k1b_norm_w(const float* __restrict__ Wm) {
    int wid = threadIdx.x >> 5, lane = threadIdx.x & 31;
    int row = blockIdx.x * 8 + wid;
    const float4* wr = (const float4*)(Wm + (size_t)row * DD);
    float4 v[4];
    float ss = 0.f;
    #pragma unroll
    for (int i = 0; i < 4; i++) {
        v[i] = wr[lane + i * 32];
        ss += v[i].x * v[i].x + v[i].y * v[i].y + v[i].z * v[i].z + v[i].w * v[i].w;
    }
    #pragma unroll
    for (int o = 16; o; o >>= 1) ss += __shfl_xor_sync(0xffffffffu, ss, o);
    float sc = 1.0f / fmaxf(sqrtf(ss), 1e-12f);
    __half2* out = (__half2*)(g_wnh + (size_t)row * DD);
    #pragma unroll
    for (int i = 0; i < 4; i++) {
        __half2 p0 = __floats2half2_rn(v[i].x * sc, v[i].y * sc);
        __half2 p1 = __floats2half2_rn(v[i].z * sc, v[i].w * sc);
        out[(lane + i * 32) * 2]     = p0;
        out[(lane + i * 32) * 2 + 1] = p1;
    }
}

// ---------------------------------------------------------------------------
// k2: fp16 HMMA GEMM (round-10 config), 256 threads / 8 warps (4x2, warp tile
// 64x64), 256Mx128N, BK=32, 3-stage cp.async (single sync/stage), 2 CTAs/SM.
// ---------------------------------------------------------------------------
__global__ __launch_bounds__(256, 2) void k2_gemm() {
    extern __shared__ char smem[];
    const uint32_t sb = (uint32_t)__cvta_generic_to_shared(smem);
    const int t = threadIdx.x, lane = t & 31, wp = t >> 5;
    const int wm = wp >> 1, wn = wp & 1;       // 4x2 warps, tile 64x64
    const int mt = blockIdx.x, nt = blockIdx.y;
    const int m0 = mt * BM, n0 = nt * BN;

    if (t < BM) ((int*)(smem + SY_OFF))[t] = g_y[m0 + t];

    // producers: A 4 rows/thread (stride 64), B 2 rows/thread (stride 64)
    const int pr = t >> 2, pc = (t & 3) * 8;
    const __half* gA = g_xnh + (m0 + pr) * DD + pc;
    const __half* gB = g_wnh + (size_t)(n0 + pr) * DD + pc;
    const uint32_t sA = sb + A_OFF + (pr * AROW + pc) * 2;
    const uint32_t sB = sb + B_OFF + (pr * AROW + pc) * 2;
    constexpr uint32_t ARS = 64 * AROW * 2;   // 64-row stride in smem bytes
    uint32_t woA = 0, woB = 0;

    auto fill = [&]() {
        cpasync16(sA + woA,           gA);
        cpasync16(sA + woA + ARS,     gA + 64 * DD);
        cpasync16(sA + woA + 2 * ARS, gA + 128 * DD);
        cpasync16(sA + woA + 3 * ARS, gA + 192 * DD);
        cpasync16(sB + woB,           gB);
        cpasync16(sB + woB + ARS,     gB + 64 * DD);
        gA += BK; gB += BK;
        woA += A_STG; if (woA == NPIPE * A_STG) woA = 0;
        woB += B_STG; if (woB == NPIPE * B_STG) woB = 0;
    };

    uint32_t acc[4][8][2];   // fp16x2 accumulators, 64 regs
    #pragma unroll
    for (int i = 0; i < 4; i++)
        #pragma unroll
        for (int j = 0; j < 8; j++) { acc[i][j][0] = 0u; acc[i][j][1] = 0u; }

    uint32_t aoff[4], boff[4];
    #pragma unroll
    for (int mf = 0; mf < 4; mf++)
        aoff[mf] = sb + A_OFF + ((wm * 64 + mf * 16 + (lane & 15)) * AROW + (lane >> 4) * 8) * 2;
    #pragma unroll
    for (int g = 0; g < 4; g++)
        boff[g] = sb + B_OFF + ((wn * 64 + g * 16 + (lane & 15)) * AROW + (lane >> 4) * 8) * 2;

    fill(); cpcommit();
    fill(); cpcommit();

    uint32_t roA = 0, roB = 0;
    for (int ks = 0; ks < NSTG; ks++) {
        cpwait1();
        __syncthreads();
        if (ks + 2 < NSTG) fill();
        cpcommit();

        #pragma unroll
        for (int kc = 0; kc < 2; kc++) {
            uint32_t bfrag[4][4];
            #pragma unroll
            for (int g = 0; g < 4; g++)
                ldsm4(bfrag[g], boff[g] + roB + kc * 32);
            #pragma unroll
            for (int mf = 0; mf < 4; mf++) {
                uint32_t afrag[4];
                ldsm4(afrag, aoff[mf] + roA + kc * 32);
                #pragma unroll
                for (int nf = 0; nf < 8; nf++) {
                    int g = nf >> 1, h = nf & 1;
                    mma16816h(acc[mf][nf], afrag, bfrag[g][h], bfrag[g][2 + h]);
                }
            }
        }
        roA += A_STG; if (roA == NPIPE * A_STG) roA = 0;
        roB += B_STG; if (roB == NPIPE * B_STG) roB = 0;
    }
    __syncthreads();

    // epilogue: theta = acc; exp + mask + row-sum
    const int* sy = (const int*)(smem + SY_OFF);
    float* rowacc = (float*)(smem + RA_OFF);
    #pragma unroll
    for (int mf = 0; mf < 4; mf++) {
        #pragma unroll
        for (int h = 0; h < 2; h++) {
            int row = wm * 64 + mf * 16 + h * 8 + (lane >> 2);
            int yrel = sy[row] - n0;
            float rsum = 0.f;
            #pragma unroll
            for (int nf = 0; nf < 8; nf++) {
                int nl = wn * 64 + nf * 8 + (lane & 3) * 2;
                float2 th = __half22float2(*(const __half2*)&acc[mf][nf][h]);
                float e0 = __expf(64.0f * th.x);
                float e1 = __expf(64.0f * th.y);
                rsum += (nl     == yrel) ? 0.f : e0;
                rsum += (nl + 1 == yrel) ? 0.f : e1;
            }
            rsum += __shfl_xor_sync(0xffffffffu, rsum, 1);
            rsum += __shfl_xor_sync(0xffffffffu, rsum, 2);
            if ((lane & 3) == 0) rowacc[row * 2 + wn] = rsum;
        }
    }
    __syncthreads();
    if (t < BM)
        g_partial[(mt * NT + nt) * BM + t] = rowacc[t * 2] + rowacc[t * 2 + 1];
}

// ---------------------------------------------------------------------------
// k3: per-row finalize (exact fp32 target logit) + fused final mean.
// 512 blocks x 512 threads; the last block to finish performs the fixed-order
// reduction over g_term (deterministic) and resets the counter.
// ---------------------------------------------------------------------------
__global__ __launch_bounds__(512) void k3_final(const float* __restrict__ Wm,
                                                float* __restrict__ out) {
    __shared__ double sd[512];
    __shared__ float  sf[128], sg[128];
    __shared__ unsigned int rank;
    int b = blockIdx.x, t = threadIdx.x;
    int yb = g_y[b];
    int mt = b >> 8, ml = b & 255;

    double ex = (t < NT) ? (double)g_partial[(mt * NT + t) * BM + ml] : 0.0;

    if (t < 128) {
        float4 wv = ((const float4*)(Wm + (size_t)yb * DD))[t];
        float4 xv = ((const float4*)(g_xn + b * DD))[t];
        sf[t] = wv.x * xv.x + wv.y * xv.y + wv.z * xv.z + wv.w * xv.w;
        sg[t] = wv.x * wv.x + wv.y * wv.y + wv.z * wv.z + wv.w * wv.w;
    }
    sd[t] = ex;
    __syncthreads();
    for (int s = 256; s >= 128; s >>= 1) {
        if (t < s) sd[t] += sd[t + s];
        __syncthreads();
    }
    for (int s = 64; s; s >>= 1) {
        if (t < s) { sd[t] += sd[t + s]; sf[t] += sf[t + s]; sg[t] += sg[t + s]; }
        __syncthreads();
    }
    if (t == 0) {
        double tgt = (double)sf[0] / fmax(sqrt((double)sg[0]), 1e-12);
        double tc = fmin(fmax(tgt, -1.0 + 1e-7), 1.0 - 1e-7);
        double num = 64.0 * cos(acos(tc) + 0.5);
        double den = exp(num) + sd[0];
        g_term[b] = num - log(den);
        __threadfence();
        rank = atomicInc(&g_k3done, 0xffffffffu);
    }
    __syncthreads();

    if (rank == BB - 1) {            // last block: deterministic final reduce
        __threadfence();
        sd[t] = g_term[t];
        __syncthreads();
        for (int s = 256; s; s >>= 1) {
            if (t < s) sd[t] += sd[t + s];
            __syncthreads();
        }
        if (t == 0) {
            out[0] = (float)(-sd[0] / (double)BB);
            g_k3done = 0;            // reset for next (graph-replayed) call
        }
    }
}

extern "C" void kernel_launch(void* const* d_in, const int* in_sizes, int n_in,
                              void* d_out, int out_size) {
    const float* x = (const float*)d_in[0];
    const int*   y = (const int*)d_in[1];
    const float* W = (const float*)d_in[2];

    cudaFuncSetAttribute(k2_gemm, cudaFuncAttributeMaxDynamicSharedMemorySize, SMEM_TOTAL);

    k1_norm_x<<<BB, 128>>>(x, y);
    k1b_norm_w<<<CC / 8, 256>>>(W);
    k2_gemm<<<dim3(MT, NT), 256, SMEM_TOTAL>>>();
    k3_final<<<BB, 512>>>(W, (float*)d_out);
}

// round 13
// speedup vs baseline: 1.0978x; 1.0032x over previous
#include <cuda_runtime.h>
#include <cuda_fp16.h>
#include <cstdint>

// ArcFace loss, fused. FP16 HMMA (m16n8k16.f16), warp tile 64x64, fp16 acc.
// This round: g_partial transposed to [row][ntile] so k3 reads are coalesced
// (scatter moved to k2's latency-tolerant store side).
// B=512, D=512, C=64000.
constexpr int BB = 512;
constexpr int DD = 512;
constexpr int CC = 64000;

constexpr int BM = 256, BN = 128, BK = 32;
constexpr int MT = BB / BM;    // 2
constexpr int NT = CC / BN;    // 500
constexpr int NSTG = DD / BK;  // 16
constexpr int AROW = 40;       // smem row stride (halfs); ldsm conflict-free
constexpr int A_STG = BM * AROW * 2;   // 20480 B
constexpr int B_STG = BN * AROW * 2;   // 10240 B
constexpr int NPIPE = 3;

// dynamic smem layout
constexpr int A_OFF  = 0;                       // 3 stages
constexpr int B_OFF  = NPIPE * A_STG;           // 61440, 3 stages
constexpr int SY_OFF = B_OFF + NPIPE * B_STG;   // 92160: 256 ints
constexpr int RA_OFF = SY_OFF + 1024;           // 93184: 256x2 floats
constexpr int SMEM_TOTAL = RA_OFF + 2048;       // 95232 (x2 CTA = 190KB <= 228KB)

__device__ float  g_xn[BB * DD];    // normalized x fp32 (k3 exact dot)
__device__ __half g_xnh[BB * DD];   // normalized x fp16 (GEMM A)
__device__ __half g_wnh[CC * DD];   // normalized W fp16 (GEMM B)
__device__ int    g_y[BB];
__device__ float  g_partial[BB * NT];  // [row][ntile] — k3-coalesced
__device__ double g_term[BB];
__device__ unsigned int g_k3done;   // zero-initialized; reset by finisher

// ---------------- PTX helpers ----------------
__device__ __forceinline__ void ldsm4(uint32_t* r, uint32_t a) {
    asm volatile("ldmatrix.sync.aligned.m8n8.x4.shared.b16 {%0,%1,%2,%3}, [%4];"
        : "=r"(r[0]), "=r"(r[1]), "=r"(r[2]), "=r"(r[3]) : "r"(a));
}
__device__ __forceinline__ void mma16816h(uint32_t* c, const uint32_t* a, uint32_t b0, uint32_t b1) {
    asm volatile("mma.sync.aligned.m16n8k16.row.col.f16.f16.f16.f16 "
        "{%0,%1}, {%2,%3,%4,%5}, {%6,%7}, {%0,%1};"
        : "+r"(c[0]), "+r"(c[1])
        : "r"(a[0]), "r"(a[1]), "r"(a[2]), "r"(a[3]), "r"(b0), "r"(b1));
}
__device__ __forceinline__ void cpasync16(uint32_t smem, const void* gptr) {
    asm volatile("cp.async.cg.shared.global [%0], [%1], 16;"
        :: "r"(smem), "l"(gptr) : "memory");
}
__device__ __forceinline__ void cpcommit() { asm volatile("cp.async.commit_group;" ::: "memory"); }
__device__ __forceinline__ void cpwait1() { asm volatile("cp.async.wait_group 1;" ::: "memory"); }

// ---------------------------------------------------------------------------
// k1: L2-normalize rows of x -> fp32 + fp16; block 0 also decodes labels
// (int64 vs int32 layout sniff: labels < 64000 -> int64 high words all zero).
// ---------------------------------------------------------------------------
__global__ void k1_norm_x(const float* __restrict__ x, const int* __restrict__ yw) {
    int row = blockIdx.x;
    int t = threadIdx.x; // 128
    float4 v = ((const float4*)(x + row * DD))[t];
    float ss = v.x * v.x + v.y * v.y + v.z * v.z + v.w * v.w;
    #pragma unroll
    for (int o = 16; o; o >>= 1) ss += __shfl_xor_sync(0xffffffffu, ss, o);
    __shared__ float ws[4];
    if ((t & 31) == 0) ws[t >> 5] = ss;
    __syncthreads();
    float tot = ws[0] + ws[1] + ws[2] + ws[3];
    float sc = 1.0f / fmaxf(sqrtf(tot), 1e-12f);
    float4 o4 = make_float4(v.x * sc, v.y * sc, v.z * sc, v.w * sc);
    ((float4*)(g_xn + row * DD))[t] = o4;
    __half2 p0 = __floats2half2_rn(o4.x, o4.y);
    __half2 p1 = __floats2half2_rn(o4.z, o4.w);
    ((__half2*)(g_xnh + row * DD))[2 * t]     = p0;
    ((__half2*)(g_xnh + row * DD))[2 * t + 1] = p1;

    if (row == 0) {
        __shared__ int oddnz;
        if (t == 0) oddnz = 0;
        __syncthreads();
        int nz = 0;
        for (int i = t; i < 256; i += 128)
            if (yw[2 * i + 1] != 0) nz = 1;
        if (nz) atomicOr(&oddnz, 1);
        __syncthreads();
        for (int i = t; i < BB; i += 128)
            g_y[i] = oddnz ? yw[i] : (int)((const long long*)yw)[i];
    }
}

// k1b: L2-normalize rows of W -> fp16. One warp per row, 8 rows per block.
__global__ __launch_bounds__(256) void k1b_norm_w(const float* __restrict__ Wm) {
    int wid = threadIdx.x >> 5, lane = threadIdx.x & 31;
    int row = blockIdx.x * 8 + wid;
    const float4* wr = (const float4*)(Wm + (size_t)row * DD);
    float4 v[4];
    float ss = 0.f;
    #pragma unroll
    for (int i = 0; i < 4; i++) {
        v[i] = wr[lane + i * 32];
        ss += v[i].x * v[i].x + v[i].y * v[i].y + v[i].z * v[i].z + v[i].w * v[i].w;
    }
    #pragma unroll
    for (int o = 16; o; o >>= 1) ss += __shfl_xor_sync(0xffffffffu, ss, o);
    float sc = 1.0f / fmaxf(sqrtf(ss), 1e-12f);
    __half2* out = (__half2*)(g_wnh + (size_t)row * DD);
    #pragma unroll
    for (int i = 0; i < 4; i++) {
        __half2 p0 = __floats2half2_rn(v[i].x * sc, v[i].y * sc);
        __half2 p1 = __floats2half2_rn(v[i].z * sc, v[i].w * sc);
        out[(lane + i * 32) * 2]     = p0;
        out[(lane + i * 32) * 2 + 1] = p1;
    }
}

// ---------------------------------------------------------------------------
// k2: fp16 HMMA GEMM, 256 threads / 8 warps (4x2, warp tile 64x64), 256Mx128N,
// BK=32, 3-stage cp.async (single sync/stage), 2 CTAs/SM.
// ---------------------------------------------------------------------------
__global__ __launch_bounds__(256, 2) void k2_gemm() {
    extern __shared__ char smem[];
    const uint32_t sb = (uint32_t)__cvta_generic_to_shared(smem);
    const int t = threadIdx.x, lane = t & 31, wp = t >> 5;
    const int wm = wp >> 1, wn = wp & 1;       // 4x2 warps, tile 64x64
    const int mt = blockIdx.x, nt = blockIdx.y;
    const int m0 = mt * BM, n0 = nt * BN;

    if (t < BM) ((int*)(smem + SY_OFF))[t] = g_y[m0 + t];

    // producers: A 4 rows/thread (stride 64), B 2 rows/thread (stride 64)
    const int pr = t >> 2, pc = (t & 3) * 8;
    const __half* gA = g_xnh + (m0 + pr) * DD + pc;
    const __half* gB = g_wnh + (size_t)(n0 + pr) * DD + pc;
    const uint32_t sA = sb + A_OFF + (pr * AROW + pc) * 2;
    const uint32_t sB = sb + B_OFF + (pr * AROW + pc) * 2;
    constexpr uint32_t ARS = 64 * AROW * 2;   // 64-row stride in smem bytes
    uint32_t woA = 0, woB = 0;

    auto fill = [&]() {
        cpasync16(sA + woA,           gA);
        cpasync16(sA + woA + ARS,     gA + 64 * DD);
        cpasync16(sA + woA + 2 * ARS, gA + 128 * DD);
        cpasync16(sA + woA + 3 * ARS, gA + 192 * DD);
        cpasync16(sB + woB,           gB);
        cpasync16(sB + woB + ARS,     gB + 64 * DD);
        gA += BK; gB += BK;
        woA += A_STG; if (woA == NPIPE * A_STG) woA = 0;
        woB += B_STG; if (woB == NPIPE * B_STG) woB = 0;
    };

    uint32_t acc[4][8][2];   // fp16x2 accumulators, 64 regs
    #pragma unroll
    for (int i = 0; i < 4; i++)
        #pragma unroll
        for (int j = 0; j < 8; j++) { acc[i][j][0] = 0u; acc[i][j][1] = 0u; }

    uint32_t aoff[4], boff[4];
    #pragma unroll
    for (int mf = 0; mf < 4; mf++)
        aoff[mf] = sb + A_OFF + ((wm * 64 + mf * 16 + (lane & 15)) * AROW + (lane >> 4) * 8) * 2;
    #pragma unroll
    for (int g = 0; g < 4; g++)
        boff[g] = sb + B_OFF + ((wn * 64 + g * 16 + (lane & 15)) * AROW + (lane >> 4) * 8) * 2;

    fill(); cpcommit();
    fill(); cpcommit();

    uint32_t roA = 0, roB = 0;
    for (int ks = 0; ks < NSTG; ks++) {
        cpwait1();
        __syncthreads();
        if (ks + 2 < NSTG) fill();
        cpcommit();

        #pragma unroll
        for (int kc = 0; kc < 2; kc++) {
            uint32_t bfrag[4][4];
            #pragma unroll
            for (int g = 0; g < 4; g++)
                ldsm4(bfrag[g], boff[g] + roB + kc * 32);
            #pragma unroll
            for (int mf = 0; mf < 4; mf++) {
                uint32_t afrag[4];
                ldsm4(afrag, aoff[mf] + roA + kc * 32);
                #pragma unroll
                for (int nf = 0; nf < 8; nf++) {
                    int g = nf >> 1, h = nf & 1;
                    mma16816h(acc[mf][nf], afrag, bfrag[g][h], bfrag[g][2 + h]);
                }
            }
        }
        roA += A_STG; if (roA == NPIPE * A_STG) roA = 0;
        roB += B_STG; if (roB == NPIPE * B_STG) roB = 0;
    }
    __syncthreads();

    // epilogue: theta = acc; exp + mask + row-sum; transposed partial store
    const int* sy = (const int*)(smem + SY_OFF);
    float* rowacc = (float*)(smem + RA_OFF);
    #pragma unroll
    for (int mf = 0; mf < 4; mf++) {
        #pragma unroll
        for (int h = 0; h < 2; h++) {
            int row = wm * 64 + mf * 16 + h * 8 + (lane >> 2);
            int yrel = sy[row] - n0;
            float rsum = 0.f;
            #pragma unroll
            for (int nf = 0; nf < 8; nf++) {
                int nl = wn * 64 + nf * 8 + (lane & 3) * 2;
                float2 th = __half22float2(*(const __half2*)&acc[mf][nf][h]);
                float e0 = __expf(64.0f * th.x);
                float e1 = __expf(64.0f * th.y);
                rsum += (nl     == yrel) ? 0.f : e0;
                rsum += (nl + 1 == yrel) ? 0.f : e1;
            }
            rsum += __shfl_xor_sync(0xffffffffu, rsum, 1);
            rsum += __shfl_xor_sync(0xffffffffu, rsum, 2);
            if ((lane & 3) == 0) rowacc[row * 2 + wn] = rsum;
        }
    }
    __syncthreads();
    if (t < BM)
        g_partial[(size_t)(m0 + t) * NT + nt] = rowacc[t * 2] + rowacc[t * 2 + 1];
}

// ---------------------------------------------------------------------------
// k3: per-row finalize (exact fp32 target logit) + fused final mean.
// 512 blocks x 512 threads; coalesced g_partial reads ([row][nt] layout);
// last block performs the fixed-order deterministic reduction.
// ---------------------------------------------------------------------------
__global__ __launch_bounds__(512) void k3_final(const float* __restrict__ Wm,
                                                float* __restrict__ out) {
    __shared__ double sd[512];
    __shared__ float  sf[128], sg[128];
    __shared__ unsigned int rank;
    int b = blockIdx.x, t = threadIdx.x;
    int yb = g_y[b];

    double ex = (t < NT) ? (double)g_partial[(size_t)b * NT + t] : 0.0;

    if (t < 128) {
        float4 wv = ((const float4*)(Wm + (size_t)yb * DD))[t];
        float4 xv = ((const float4*)(g_xn + b * DD))[t];
        sf[t] = wv.x * xv.x + wv.y * xv.y + wv.z * xv.z + wv.w * xv.w;
        sg[t] = wv.x * wv.x + wv.y * wv.y + wv.z * wv.z + wv.w * wv.w;
    }
    sd[t] = ex;
    __syncthreads();
    for (int s = 256; s >= 128; s >>= 1) {
        if (t < s) sd[t] += sd[t + s];
        __syncthreads();
    }
    for (int s = 64; s; s >>= 1) {
        if (t < s) { sd[t] += sd[t + s]; sf[t] += sf[t + s]; sg[t] += sg[t + s]; }
        __syncthreads();
    }
    if (t == 0) {
        double tgt = (double)sf[0] / fmax(sqrt((double)sg[0]), 1e-12);
        double tc = fmin(fmax(tgt, -1.0 + 1e-7), 1.0 - 1e-7);
        double num = 64.0 * cos(acos(tc) + 0.5);
        double den = exp(num) + sd[0];
        g_term[b] = num - log(den);
        __threadfence();
        rank = atomicInc(&g_k3done, 0xffffffffu);
    }
    __syncthreads();

    if (rank == BB - 1) {            // last block: deterministic final reduce
        __threadfence();
        sd[t] = g_term[t];
        __syncthreads();
        for (int s = 256; s; s >>= 1) {
            if (t < s) sd[t] += sd[t + s];
            __syncthreads();
        }
        if (t == 0) {
            out[0] = (float)(-sd[0] / (double)BB);
            g_k3done = 0;            // reset for next (graph-replayed) call
        }
    }
}

extern "C" void kernel_launch(void* const* d_in, const int* in_sizes, int n_in,
                              void* d_out, int out_size) {
    const float* x = (const float*)d_in[0];
    const int*   y = (const int*)d_in[1];
    const float* W = (const float*)d_in[2];

    cudaFuncSetAttribute(k2_gemm, cudaFuncAttributeMaxDynamicSharedMemorySize, SMEM_TOTAL);

    k1_norm_x<<<BB, 128>>>(x, y);
    k1b_norm_w<<<CC / 8, 256>>>(W);
    k2_gemm<<<dim3(MT, NT), 256, SMEM_TOTAL>>>();
    k3_final<<<BB, 512>>>(W, (float*)d_out);
}